// round 1
// baseline (speedup 1.0000x reference)
#include <cuda_runtime.h>
#include <math.h>

#define B_ 2
#define N_ 2048
#define D_ 1024
#define H_ 16
#define DH_ 64
#define SCALE_ 0.125f   /* 64^-0.5 */

/* ------------------------------------------------------------------ */
/* device scratch (allocation-free rule: __device__ globals)           */
/* ------------------------------------------------------------------ */
__device__ float g_q [B_ * H_ * N_ * DH_];   /* [B,H,N,DH]  16 MB */
__device__ float g_k [B_ * H_ * N_ * DH_];
__device__ float g_v [B_ * H_ * N_ * DH_];
__device__ float g_ao[B_ * N_ * D_];         /* attention out [B,N,D] */

/* ------------------------------------------------------------------ */
/* Tiled SGEMM: C[m,j] = sum_k A[m,k] * W[j,k]   (both row-major)      */
/* 64x64 tile, BK=16, 256 threads, 4x4 micro-tile per thread.         */
/* MODE 0: scatter into g_q/g_k/g_v head layout. MODE 1: plain store. */
/* ------------------------------------------------------------------ */
template <int MODE>
__global__ void __launch_bounds__(256)
sgemm_kernel(const float* __restrict__ A,
             const float* __restrict__ W,
             float* __restrict__ C,
             int K, int Nout)
{
    __shared__ float As[16][65];
    __shared__ float Ws[16][65];

    const int tid = threadIdx.x;
    const int m0  = blockIdx.y * 64;
    const int j0  = blockIdx.x * 64;
    const int tx  = tid & 15;
    const int ty  = tid >> 4;

    float acc[4][4];
#pragma unroll
    for (int i = 0; i < 4; i++)
#pragma unroll
        for (int j = 0; j < 4; j++) acc[i][j] = 0.f;

    for (int k0 = 0; k0 < K; k0 += 16) {
        __syncthreads();
#pragma unroll
        for (int p = 0; p < 4; p++) {
            int mm = ty + p * 16;
            As[tx][mm] = A[(m0 + mm) * K + k0 + tx];
            Ws[tx][mm] = W[(j0 + mm) * K + k0 + tx];
        }
        __syncthreads();
#pragma unroll
        for (int kk = 0; kk < 16; kk++) {
            float a[4], b[4];
#pragma unroll
            for (int i = 0; i < 4; i++) a[i] = As[kk][ty * 4 + i];
#pragma unroll
            for (int i = 0; i < 4; i++) b[i] = Ws[kk][tx * 4 + i];
#pragma unroll
            for (int i = 0; i < 4; i++)
#pragma unroll
                for (int j = 0; j < 4; j++)
                    acc[i][j] = fmaf(a[i], b[j], acc[i][j]);
        }
    }

#pragma unroll
    for (int i = 0; i < 4; i++) {
#pragma unroll
        for (int j = 0; j < 4; j++) {
            int m  = m0 + ty * 4 + i;
            int jg = j0 + tx * 4 + j;
            float v = acc[i][j];
            if (MODE == 0) {
                /* qkv column jg = s*1024 + h*64 + dh */
                int s  = jg >> 10;
                int r  = jg & 1023;
                int h  = r >> 6;
                int dh = r & 63;
                int b  = m >> 11;          /* N_ = 2048 */
                int n  = m & 2047;
                int idx = ((b * H_ + h) * N_ + n) * DH_ + dh;
                float* dst = (s == 0) ? g_q : (s == 1) ? g_k : g_v;
                dst[idx] = v;
            } else {
                C[m * Nout + jg] = v;
            }
        }
    }
}

/* ------------------------------------------------------------------ */
/* Flash-attention (fp32, online softmax).                             */
/* Block = 64 query rows of one (b,h). 256 threads: thread t owns      */
/* row = t/4, a 16-wide column/DH segment = (t%4)*16.                  */
/* Causal: kv tile loop stops at the diagonal tile.                    */
/* smem: Qs,Ks,Vs,Ps each [64][65] fp32 -> 66,560 B dynamic.           */
/* ------------------------------------------------------------------ */
__global__ void __launch_bounds__(256)
attn_kernel()
{
    extern __shared__ float sm[];
    float* Qs = sm;                 /* [64][65] */
    float* Ks = Qs + 64 * 65;
    float* Vs = Ks + 64 * 65;
    float* Ps = Vs + 64 * 65;

    const int qt  = blockIdx.x;     /* query tile 0..31 */
    const int bh  = blockIdx.y;     /* b*H + h          */
    const int tid = threadIdx.x;

    const float* Qb = g_q + (size_t)bh * N_ * DH_;
    const float* Kb = g_k + (size_t)bh * N_ * DH_;
    const float* Vb = g_v + (size_t)bh * N_ * DH_;

    /* load Q tile, fold in softmax scale */
    for (int i = tid; i < 64 * 64; i += 256) {
        int r = i >> 6, c = i & 63;
        Qs[r * 65 + c] = Qb[(qt * 64 + r) * 64 + c] * SCALE_;
    }

    const int row = tid >> 2;         /* 0..63  */
    const int c0  = (tid & 3) * 16;   /* 0,16,32,48 */

    float o[16];
#pragma unroll
    for (int i = 0; i < 16; i++) o[i] = 0.f;
    float mrow = -INFINITY, lrow = 0.f;

    for (int jt = 0; jt <= qt; jt++) {
        __syncthreads();              /* prev O-update done; Q ready on jt=0 */
        for (int i = tid; i < 64 * 64; i += 256) {
            int r = i >> 6, c = i & 63;
            Ks[r * 65 + c] = Kb[(jt * 64 + r) * 64 + c];
            Vs[r * 65 + c] = Vb[(jt * 64 + r) * 64 + c];
        }
        __syncthreads();

        /* S = Q K^T for this thread's 16 columns */
        float s[16];
#pragma unroll
        for (int i = 0; i < 16; i++) s[i] = 0.f;
#pragma unroll 4
        for (int kk = 0; kk < 64; kk++) {
            float qv = Qs[row * 65 + kk];
#pragma unroll
            for (int i = 0; i < 16; i++)
                s[i] = fmaf(qv, Ks[(c0 + i) * 65 + kk], s[i]);
        }

        if (jt == qt) {               /* diagonal tile: causal mask */
#pragma unroll
            for (int i = 0; i < 16; i++)
                if (c0 + i > row) s[i] = -INFINITY;
        }

        /* online softmax */
        float mt = s[0];
#pragma unroll
        for (int i = 1; i < 16; i++) mt = fmaxf(mt, s[i]);
        mt = fmaxf(mt, __shfl_xor_sync(0xffffffffu, mt, 1));
        mt = fmaxf(mt, __shfl_xor_sync(0xffffffffu, mt, 2));

        float mnew  = fmaxf(mrow, mt);
        float alpha = __expf(mrow - mnew);   /* exp(-inf)=0 on first tile */
        float psum  = 0.f;
#pragma unroll
        for (int i = 0; i < 16; i++) {
            float p = __expf(s[i] - mnew);
            Ps[row * 65 + c0 + i] = p;
            psum += p;
        }
        psum += __shfl_xor_sync(0xffffffffu, psum, 1);
        psum += __shfl_xor_sync(0xffffffffu, psum, 2);
        lrow = lrow * alpha + psum;
#pragma unroll
        for (int i = 0; i < 16; i++) o[i] *= alpha;
        mrow = mnew;

        __syncthreads();              /* Ps complete */

        /* O += P V for this thread's 16-wide DH segment */
#pragma unroll 4
        for (int j = 0; j < 64; j++) {
            float pv = Ps[row * 65 + j];
#pragma unroll
            for (int i = 0; i < 16; i++)
                o[i] = fmaf(pv, Vs[j * 65 + c0 + i], o[i]);
        }
    }

    const float inv = 1.f / lrow;
    const int b = bh / H_, h = bh % H_;
    float* dst = g_ao + (size_t)(b * N_ + qt * 64 + row) * D_ + h * DH_ + c0;
#pragma unroll
    for (int i = 0; i < 16; i++) dst[i] = o[i] * inv;
}

/* ------------------------------------------------------------------ */
extern "C" void kernel_launch(void* const* d_in, const int* in_sizes, int n_in,
                              void* d_out, int out_size)
{
    const float* x    = (const float*)d_in[0];
    /* d_in[1] = mask (int32 tril) — causal structure is static, unused */
    const float* Wqkv = (const float*)d_in[2];
    const float* Wout = (const float*)d_in[3];
    float* out = (float*)d_out;

    float* ao_ptr = nullptr;
    cudaGetSymbolAddress((void**)&ao_ptr, g_ao);

    /* 1. QKV projection, scattered into [B,H,N,DH] head layout */
    sgemm_kernel<0><<<dim3(3072 / 64, 4096 / 64), 256>>>(x, Wqkv, nullptr, D_, 3 * D_);

    /* 2. causal flash attention */
    const int ATT_SMEM = 4 * 64 * 65 * (int)sizeof(float);   /* 66,560 B */
    cudaFuncSetAttribute(attn_kernel,
                         cudaFuncAttributeMaxDynamicSharedMemorySize, ATT_SMEM);
    attn_kernel<<<dim3(N_ / 64, B_ * H_), 256, ATT_SMEM>>>();

    /* 3. output projection -> d_out */
    sgemm_kernel<1><<<dim3(1024 / 64, 4096 / 64), 256>>>(ao_ptr, Wout, out, D_, D_);
}

// round 3
// speedup vs baseline: 1.3072x; 1.3072x over previous
#include <cuda_runtime.h>
#include <cuda_bf16.h>
#include <math.h>
#include <stdint.h>

#define B_ 2
#define N_ 2048
#define D_ 1024
#define H_ 16
#define DH_ 64
#define SCALE_ 0.125f   /* 64^-0.5 */

/* ------------------------------------------------------------------ */
/* device scratch                                                      */
/* ------------------------------------------------------------------ */
__device__ float g_q [B_ * H_ * N_ * DH_];
__device__ float g_k [B_ * H_ * N_ * DH_];
__device__ float g_v [B_ * H_ * N_ * DH_];
__device__ float g_ao[B_ * N_ * D_];

/* ------------------------------------------------------------------ */
/* warp-mma helpers (generic PTX: ldmatrix sm_75+, mma.sync sm_80+)    */
/* ------------------------------------------------------------------ */
__device__ __forceinline__ uint32_t smem_u32(const void* p) {
    uint32_t a;
    asm("{ .reg .u64 t; cvta.to.shared.u64 t, %1; cvt.u32.u64 %0, t; }"
        : "=r"(a) : "l"(p));
    return a;
}

__device__ __forceinline__ void ldsm4(uint32_t addr, uint32_t& r0, uint32_t& r1,
                                      uint32_t& r2, uint32_t& r3) {
    asm volatile("ldmatrix.sync.aligned.m8n8.x4.shared.b16 {%0,%1,%2,%3}, [%4];"
                 : "=r"(r0), "=r"(r1), "=r"(r2), "=r"(r3) : "r"(addr));
}

__device__ __forceinline__ void mma16816(float* c,
                                         uint32_t a0, uint32_t a1, uint32_t a2, uint32_t a3,
                                         uint32_t b0, uint32_t b1) {
    asm volatile(
        "mma.sync.aligned.m16n8k16.row.col.f32.bf16.bf16.f32 "
        "{%0,%1,%2,%3}, {%4,%5,%6,%7}, {%8,%9}, {%0,%1,%2,%3};"
        : "+f"(c[0]), "+f"(c[1]), "+f"(c[2]), "+f"(c[3])
        : "r"(a0), "r"(a1), "r"(a2), "r"(a3), "r"(b0), "r"(b1));
}

/* ------------------------------------------------------------------ */
/* loader: 128x32 fp32 subtile -> hi/lo bf16 smem, stride 40 bf16      */
/* ------------------------------------------------------------------ */
#define TSTR 40   /* smem row stride in bf16 elements */

__device__ __forceinline__ void load_split(const float* __restrict__ src, int ldk,
                                           __nv_bfloat16* th, __nv_bfloat16* tl,
                                           int tid) {
#pragma unroll
    for (int it = 0; it < 4; it++) {
        int idx = tid + it * 256;          /* 0..1023 float4 slots */
        int r   = idx >> 3;                /* row 0..127           */
        int c4  = idx & 7;                 /* float4 col 0..7      */
        float4 v = *reinterpret_cast<const float4*>(src + (size_t)r * ldk + c4 * 4);

        __nv_bfloat162 h01 = __floats2bfloat162_rn(v.x, v.y);
        __nv_bfloat162 h23 = __floats2bfloat162_rn(v.z, v.w);
        float rx = v.x - __bfloat162float(h01.x);
        float ry = v.y - __bfloat162float(h01.y);
        float rz = v.z - __bfloat162float(h23.x);
        float rw = v.w - __bfloat162float(h23.y);
        __nv_bfloat162 l01 = __floats2bfloat162_rn(rx, ry);
        __nv_bfloat162 l23 = __floats2bfloat162_rn(rz, rw);

        int off = r * TSTR + c4 * 4;       /* byte offset = 80r + 8c4 (8B aligned) */
        *reinterpret_cast<uint2*>(th + off) =
            make_uint2(*reinterpret_cast<uint32_t*>(&h01),
                       *reinterpret_cast<uint32_t*>(&h23));
        *reinterpret_cast<uint2*>(tl + off) =
            make_uint2(*reinterpret_cast<uint32_t*>(&l01),
                       *reinterpret_cast<uint32_t*>(&l23));
    }
}

/* ------------------------------------------------------------------ */
/* HMMA GEMM: C[m,j] = sum_k A[m,k] * W[j,k], fp32 via bf16 hi/lo.     */
/* tile 128x128, BK=32, 256 thr (8 warps, 4x2). MODE0: qkv scatter.    */
/* ------------------------------------------------------------------ */
template <int MODE>
__global__ void __launch_bounds__(256)
gemm_hmma(const float* __restrict__ A, const float* __restrict__ W,
          float* __restrict__ C, int K, int Nout)
{
    __shared__ __nv_bfloat16 As_h[128 * TSTR];
    __shared__ __nv_bfloat16 As_l[128 * TSTR];
    __shared__ __nv_bfloat16 Ws_h[128 * TSTR];
    __shared__ __nv_bfloat16 Ws_l[128 * TSTR];

    const int tid  = threadIdx.x;
    const int lane = tid & 31;
    const int wid  = tid >> 5;
    const int wm   = wid & 3;        /* 0..3 -> 32-row slice  */
    const int wn   = wid >> 2;       /* 0..1 -> 64-col slice  */

    const int m0 = blockIdx.y * 128;
    const int j0 = blockIdx.x * 128;

    const uint32_t sAh = smem_u32(As_h);
    const uint32_t sAl = smem_u32(As_l);
    const uint32_t sWh = smem_u32(Ws_h);
    const uint32_t sWl = smem_u32(Ws_l);

    /* per-lane ldmatrix address components */
    const int arow = wm * 32 + (lane & 15);
    const int acol = (lane >> 4) << 3;
    const int brow = wn * 64 + ((lane & 7) | ((lane & 16) >> 1));
    const int bcol = lane & 8;

    float acc[2][8][4];
#pragma unroll
    for (int i = 0; i < 2; i++)
#pragma unroll
        for (int j = 0; j < 8; j++)
#pragma unroll
            for (int c = 0; c < 4; c++) acc[i][j][c] = 0.f;

    const int nchunk = K >> 5;   /* K / 32 */
    for (int kc = 0; kc < nchunk; kc++) {
        __syncthreads();
        load_split(A + (size_t)m0 * K + kc * 32, K, As_h, As_l, tid);
        load_split(W + (size_t)j0 * K + kc * 32, K, Ws_h, Ws_l, tid);
        __syncthreads();

#pragma unroll
        for (int ks = 0; ks < 2; ks++) {
            const uint32_t aoff = 2u * ((uint32_t)(arow * TSTR) + ks * 16 + acol);
            uint32_t ah[2][4], al[2][4];
#pragma unroll
            for (int mt = 0; mt < 2; mt++) {
                uint32_t d = aoff + 2u * (mt * 16 * TSTR);
                ldsm4(sAh + d, ah[mt][0], ah[mt][1], ah[mt][2], ah[mt][3]);
                ldsm4(sAl + d, al[mt][0], al[mt][1], al[mt][2], al[mt][3]);
            }
#pragma unroll
            for (int np = 0; np < 4; np++) {
                const uint32_t boff =
                    2u * ((uint32_t)((brow + np * 16) * TSTR) + ks * 16 + bcol);
                uint32_t bh[4], bl[4];
                ldsm4(sWh + boff, bh[0], bh[1], bh[2], bh[3]);
                ldsm4(sWl + boff, bl[0], bl[1], bl[2], bl[3]);
#pragma unroll
                for (int mt = 0; mt < 2; mt++) {
#pragma unroll
                    for (int sub = 0; sub < 2; sub++) {
                        float* c = acc[mt][np * 2 + sub];
                        mma16816(c, ah[mt][0], ah[mt][1], ah[mt][2], ah[mt][3],
                                 bh[sub * 2], bh[sub * 2 + 1]);
                        mma16816(c, ah[mt][0], ah[mt][1], ah[mt][2], ah[mt][3],
                                 bl[sub * 2], bl[sub * 2 + 1]);
                        mma16816(c, al[mt][0], al[mt][1], al[mt][2], al[mt][3],
                                 bh[sub * 2], bh[sub * 2 + 1]);
                    }
                }
            }
        }
    }

    /* epilogue */
    const int grp = lane >> 2;
    const int qid = lane & 3;
#pragma unroll
    for (int mt = 0; mt < 2; mt++) {
#pragma unroll
        for (int nt = 0; nt < 8; nt++) {
            const float* c = acc[mt][nt];
            int row = m0 + wm * 32 + mt * 16 + grp;
            int col = j0 + wn * 64 + nt * 8 + qid * 2;
#pragma unroll
            for (int half = 0; half < 2; half++) {
                int m = row + half * 8;
                float2 v = make_float2(c[half * 2], c[half * 2 + 1]);
                if (MODE == 0) {
                    int s  = col >> 10;
                    int rr = col & 1023;
                    int h  = rr >> 6;
                    int dh = rr & 63;
                    int b  = m >> 11;
                    int n  = m & 2047;
                    float* base = (s == 0) ? g_q : (s == 1) ? g_k : g_v;
                    *reinterpret_cast<float2*>(
                        base + (((size_t)(b * H_ + h) * N_ + n) * DH_ + dh)) = v;
                } else {
                    *reinterpret_cast<float2*>(C + (size_t)m * Nout + col) = v;
                }
            }
        }
    }
}

/* ------------------------------------------------------------------ */
/* Flash-attention (fp32, online softmax) — unchanged from R1          */
/* ------------------------------------------------------------------ */
__global__ void __launch_bounds__(256)
attn_kernel()
{
    extern __shared__ float smf[];
    float* Qs = smf;
    float* Ks = Qs + 64 * 65;
    float* Vs = Ks + 64 * 65;
    float* Ps = Vs + 64 * 65;

    const int qt  = blockIdx.x;
    const int bh  = blockIdx.y;
    const int tid = threadIdx.x;

    const float* Qb = g_q + (size_t)bh * N_ * DH_;
    const float* Kb = g_k + (size_t)bh * N_ * DH_;
    const float* Vb = g_v + (size_t)bh * N_ * DH_;

    for (int i = tid; i < 64 * 64; i += 256) {
        int r = i >> 6, c = i & 63;
        Qs[r * 65 + c] = Qb[(qt * 64 + r) * 64 + c] * SCALE_;
    }

    const int row = tid >> 2;
    const int c0  = (tid & 3) * 16;

    float o[16];
#pragma unroll
    for (int i = 0; i < 16; i++) o[i] = 0.f;
    float mrow = -INFINITY, lrow = 0.f;

    for (int jt = 0; jt <= qt; jt++) {
        __syncthreads();
        for (int i = tid; i < 64 * 64; i += 256) {
            int r = i >> 6, c = i & 63;
            Ks[r * 65 + c] = Kb[(jt * 64 + r) * 64 + c];
            Vs[r * 65 + c] = Vb[(jt * 64 + r) * 64 + c];
        }
        __syncthreads();

        float s[16];
#pragma unroll
        for (int i = 0; i < 16; i++) s[i] = 0.f;
#pragma unroll 4
        for (int kk = 0; kk < 64; kk++) {
            float qv = Qs[row * 65 + kk];
#pragma unroll
            for (int i = 0; i < 16; i++)
                s[i] = fmaf(qv, Ks[(c0 + i) * 65 + kk], s[i]);
        }

        if (jt == qt) {
#pragma unroll
            for (int i = 0; i < 16; i++)
                if (c0 + i > row) s[i] = -INFINITY;
        }

        float mt = s[0];
#pragma unroll
        for (int i = 1; i < 16; i++) mt = fmaxf(mt, s[i]);
        mt = fmaxf(mt, __shfl_xor_sync(0xffffffffu, mt, 1));
        mt = fmaxf(mt, __shfl_xor_sync(0xffffffffu, mt, 2));

        float mnew  = fmaxf(mrow, mt);
        float alpha = __expf(mrow - mnew);
        float psum  = 0.f;
#pragma unroll
        for (int i = 0; i < 16; i++) {
            float p = __expf(s[i] - mnew);
            Ps[row * 65 + c0 + i] = p;
            psum += p;
        }
        psum += __shfl_xor_sync(0xffffffffu, psum, 1);
        psum += __shfl_xor_sync(0xffffffffu, psum, 2);
        lrow = lrow * alpha + psum;
#pragma unroll
        for (int i = 0; i < 16; i++) o[i] *= alpha;
        mrow = mnew;

        __syncthreads();

#pragma unroll 4
        for (int j = 0; j < 64; j++) {
            float pv = Ps[row * 65 + j];
#pragma unroll
            for (int i = 0; i < 16; i++)
                o[i] = fmaf(pv, Vs[j * 65 + c0 + i], o[i]);
        }
    }

    const float inv = 1.f / lrow;
    const int b = bh / H_, h = bh % H_;
    float* dst = g_ao + (size_t)(b * N_ + qt * 64 + row) * D_ + h * DH_ + c0;
#pragma unroll
    for (int i = 0; i < 16; i++) dst[i] = o[i] * inv;
}

/* ------------------------------------------------------------------ */
extern "C" void kernel_launch(void* const* d_in, const int* in_sizes, int n_in,
                              void* d_out, int out_size)
{
    const float* x    = (const float*)d_in[0];
    /* d_in[1] = mask (static causal structure, unused) */
    const float* Wqkv = (const float*)d_in[2];
    const float* Wout = (const float*)d_in[3];
    float* out = (float*)d_out;

    float* ao_ptr = nullptr;
    cudaGetSymbolAddress((void**)&ao_ptr, g_ao);

    /* 1. QKV projection (HMMA bf16-split), scatter into [B,H,N,DH] */
    gemm_hmma<0><<<dim3(3072 / 128, 4096 / 128), 256>>>(x, Wqkv, nullptr, D_, 3 * D_);

    /* 2. causal flash attention (fp32) */
    const int ATT_SMEM = 4 * 64 * 65 * (int)sizeof(float);
    cudaFuncSetAttribute(attn_kernel,
                         cudaFuncAttributeMaxDynamicSharedMemorySize, ATT_SMEM);
    attn_kernel<<<dim3(N_ / 64, B_ * H_), 256, ATT_SMEM>>>();

    /* 3. output projection (HMMA bf16-split) -> d_out */
    gemm_hmma<1><<<dim3(1024 / 128, 4096 / 128), 256>>>(ao_ptr, Wout, out, D_, D_);
}

// round 4
// speedup vs baseline: 6.3588x; 4.8645x over previous
#include <cuda_runtime.h>
#include <cuda_bf16.h>
#include <math.h>
#include <stdint.h>

#define B_ 2
#define N_ 2048
#define D_ 1024
#define H_ 16
#define DH_ 64
#define SCALE_ 0.125f   /* 64^-0.5 */

/* ------------------------------------------------------------------ */
/* device scratch                                                      */
/* ------------------------------------------------------------------ */
__device__ float g_q [B_ * H_ * N_ * DH_];
__device__ float g_k [B_ * H_ * N_ * DH_];
__device__ float g_v [B_ * H_ * N_ * DH_];
__device__ float g_ao[B_ * N_ * D_];

/* ------------------------------------------------------------------ */
/* warp-mma helpers (generic PTX: ldmatrix sm_75+, mma.sync sm_80+)    */
/* ------------------------------------------------------------------ */
__device__ __forceinline__ uint32_t smem_u32(const void* p) {
    uint32_t a;
    asm("{ .reg .u64 t; cvta.to.shared.u64 t, %1; cvt.u32.u64 %0, t; }"
        : "=r"(a) : "l"(p));
    return a;
}

__device__ __forceinline__ void ldsm4(uint32_t addr, uint32_t& r0, uint32_t& r1,
                                      uint32_t& r2, uint32_t& r3) {
    asm volatile("ldmatrix.sync.aligned.m8n8.x4.shared.b16 {%0,%1,%2,%3}, [%4];"
                 : "=r"(r0), "=r"(r1), "=r"(r2), "=r"(r3) : "r"(addr));
}

__device__ __forceinline__ void mma16816(float* c,
                                         uint32_t a0, uint32_t a1, uint32_t a2, uint32_t a3,
                                         uint32_t b0, uint32_t b1) {
    asm volatile(
        "mma.sync.aligned.m16n8k16.row.col.f32.bf16.bf16.f32 "
        "{%0,%1,%2,%3}, {%4,%5,%6,%7}, {%8,%9}, {%0,%1,%2,%3};"
        : "+f"(c[0]), "+f"(c[1]), "+f"(c[2]), "+f"(c[3])
        : "r"(a0), "r"(a1), "r"(a2), "r"(a3), "r"(b0), "r"(b1));
}

/* split a float pair into packed bf16x2 hi and lo words */
__device__ __forceinline__ void split2(float x, float y, uint32_t& hi, uint32_t& lo) {
    __nv_bfloat162 h = __floats2bfloat162_rn(x, y);
    float rx = x - __bfloat162float(h.x);
    float ry = y - __bfloat162float(h.y);
    __nv_bfloat162 l = __floats2bfloat162_rn(rx, ry);
    hi = *reinterpret_cast<uint32_t*>(&h);
    lo = *reinterpret_cast<uint32_t*>(&l);
}

/* ------------------------------------------------------------------ */
/* GEMM (unchanged from R3): C[m,j]=sum_k A[m,k]W[j,k], bf16 hi/lo     */
/* ------------------------------------------------------------------ */
#define TSTR 40

__device__ __forceinline__ void load_split(const float* __restrict__ src, int ldk,
                                           __nv_bfloat16* th, __nv_bfloat16* tl,
                                           int tid) {
#pragma unroll
    for (int it = 0; it < 4; it++) {
        int idx = tid + it * 256;
        int r   = idx >> 3;
        int c4  = idx & 7;
        float4 v = *reinterpret_cast<const float4*>(src + (size_t)r * ldk + c4 * 4);
        uint32_t h0, l0, h1, l1;
        split2(v.x, v.y, h0, l0);
        split2(v.z, v.w, h1, l1);
        int off = r * TSTR + c4 * 4;
        *reinterpret_cast<uint2*>(th + off) = make_uint2(h0, h1);
        *reinterpret_cast<uint2*>(tl + off) = make_uint2(l0, l1);
    }
}

template <int MODE>
__global__ void __launch_bounds__(256)
gemm_hmma(const float* __restrict__ A, const float* __restrict__ W,
          float* __restrict__ C, int K, int Nout)
{
    __shared__ __nv_bfloat16 As_h[128 * TSTR];
    __shared__ __nv_bfloat16 As_l[128 * TSTR];
    __shared__ __nv_bfloat16 Ws_h[128 * TSTR];
    __shared__ __nv_bfloat16 Ws_l[128 * TSTR];

    const int tid  = threadIdx.x;
    const int lane = tid & 31;
    const int wid  = tid >> 5;
    const int wm   = wid & 3;
    const int wn   = wid >> 2;

    const int m0 = blockIdx.y * 128;
    const int j0 = blockIdx.x * 128;

    const uint32_t sAh = smem_u32(As_h);
    const uint32_t sAl = smem_u32(As_l);
    const uint32_t sWh = smem_u32(Ws_h);
    const uint32_t sWl = smem_u32(Ws_l);

    const int arow = wm * 32 + (lane & 15);
    const int acol = (lane >> 4) << 3;
    const int brow = wn * 64 + ((lane & 7) | ((lane & 16) >> 1));
    const int bcol = lane & 8;

    float acc[2][8][4];
#pragma unroll
    for (int i = 0; i < 2; i++)
#pragma unroll
        for (int j = 0; j < 8; j++)
#pragma unroll
            for (int c = 0; c < 4; c++) acc[i][j][c] = 0.f;

    const int nchunk = K >> 5;
    for (int kc = 0; kc < nchunk; kc++) {
        __syncthreads();
        load_split(A + (size_t)m0 * K + kc * 32, K, As_h, As_l, tid);
        load_split(W + (size_t)j0 * K + kc * 32, K, Ws_h, Ws_l, tid);
        __syncthreads();

#pragma unroll
        for (int ks = 0; ks < 2; ks++) {
            const uint32_t aoff = 2u * ((uint32_t)(arow * TSTR) + ks * 16 + acol);
            uint32_t ah[2][4], al[2][4];
#pragma unroll
            for (int mt = 0; mt < 2; mt++) {
                uint32_t d = aoff + 2u * (mt * 16 * TSTR);
                ldsm4(sAh + d, ah[mt][0], ah[mt][1], ah[mt][2], ah[mt][3]);
                ldsm4(sAl + d, al[mt][0], al[mt][1], al[mt][2], al[mt][3]);
            }
#pragma unroll
            for (int np = 0; np < 4; np++) {
                const uint32_t boff =
                    2u * ((uint32_t)((brow + np * 16) * TSTR) + ks * 16 + bcol);
                uint32_t bh[4], bl[4];
                ldsm4(sWh + boff, bh[0], bh[1], bh[2], bh[3]);
                ldsm4(sWl + boff, bl[0], bl[1], bl[2], bl[3]);
#pragma unroll
                for (int mt = 0; mt < 2; mt++) {
#pragma unroll
                    for (int sub = 0; sub < 2; sub++) {
                        float* c = acc[mt][np * 2 + sub];
                        mma16816(c, ah[mt][0], ah[mt][1], ah[mt][2], ah[mt][3],
                                 bh[sub * 2], bh[sub * 2 + 1]);
                        mma16816(c, ah[mt][0], ah[mt][1], ah[mt][2], ah[mt][3],
                                 bl[sub * 2], bl[sub * 2 + 1]);
                        mma16816(c, al[mt][0], al[mt][1], al[mt][2], al[mt][3],
                                 bh[sub * 2], bh[sub * 2 + 1]);
                    }
                }
            }
        }
    }

    const int grp = lane >> 2;
    const int qid = lane & 3;
#pragma unroll
    for (int mt = 0; mt < 2; mt++) {
#pragma unroll
        for (int nt = 0; nt < 8; nt++) {
            const float* c = acc[mt][nt];
            int row = m0 + wm * 32 + mt * 16 + grp;
            int col = j0 + wn * 64 + nt * 8 + qid * 2;
#pragma unroll
            for (int half = 0; half < 2; half++) {
                int m = row + half * 8;
                float2 v = make_float2(c[half * 2], c[half * 2 + 1]);
                if (MODE == 0) {
                    int s  = col >> 10;
                    int rr = col & 1023;
                    int h  = rr >> 6;
                    int dh = rr & 63;
                    int b  = m >> 11;
                    int n  = m & 2047;
                    float* base = (s == 0) ? g_q : (s == 1) ? g_k : g_v;
                    *reinterpret_cast<float2*>(
                        base + (((size_t)(b * H_ + h) * N_ + n) * DH_ + dh)) = v;
                } else {
                    *reinterpret_cast<float2*>(C + (size_t)m * Nout + col) = v;
                }
            }
        }
    }
}

/* ------------------------------------------------------------------ */
/* Flash-attention on HMMA. CTA = 128 q-rows of one (b,h); 8 warps x   */
/* 16 rows. KV tiles of 64. Q,K,P,V all bf16 hi/lo split (3-MMA).      */
/* smem stride 72 bf16 (conflict-free ldmatrix).                       */
/* ------------------------------------------------------------------ */
#define ASTR 72
#define SM_QH 0
#define SM_QL (128 * ASTR)
#define SM_KH (2 * 128 * ASTR)
#define SM_KL (SM_KH + 64 * ASTR)
#define SM_VH (SM_KL + 64 * ASTR)
#define SM_VL (SM_VH + 64 * ASTR)
#define ATT_SMEM_ELEMS (SM_VL + 64 * ASTR)   /* 36864 bf16 = 73728 B */

__global__ void __launch_bounds__(256)
attn_mma()
{
    extern __shared__ __nv_bfloat16 sb[];
    __nv_bfloat16* QH = sb + SM_QH;
    __nv_bfloat16* QL = sb + SM_QL;
    __nv_bfloat16* KH = sb + SM_KH;
    __nv_bfloat16* KL = sb + SM_KL;
    __nv_bfloat16* VH = sb + SM_VH;
    __nv_bfloat16* VL = sb + SM_VL;

    const int qt = (N_ / 128 - 1) - (blockIdx.x >> 5);  /* heavy tiles first */
    const int bh = blockIdx.x & 31;
    const int b  = bh >> 4;
    const int h  = bh & 15;

    const int tid  = threadIdx.x;
    const int lane = tid & 31;
    const int w    = tid >> 5;

    const float* Qb = g_q + (size_t)bh * N_ * DH_;
    const float* Kb = g_k + (size_t)bh * N_ * DH_;
    const float* Vb = g_v + (size_t)bh * N_ * DH_;

    /* ---- load Q tile (scaled), split hi/lo ---- */
#pragma unroll
    for (int it = 0; it < 8; it++) {
        int idx = tid + it * 256;            /* 0..2047 */
        int r   = idx >> 4;
        int c4  = (idx & 15) * 4;
        float4 v = *reinterpret_cast<const float4*>(
            Qb + (size_t)(qt * 128 + r) * DH_ + c4);
        uint32_t h0, l0, h1, l1;
        split2(v.x * SCALE_, v.y * SCALE_, h0, l0);
        split2(v.z * SCALE_, v.w * SCALE_, h1, l1);
        *reinterpret_cast<uint2*>(QH + r * ASTR + c4) = make_uint2(h0, h1);
        *reinterpret_cast<uint2*>(QL + r * ASTR + c4) = make_uint2(l0, l1);
    }
    __syncthreads();

    const uint32_t sQH = smem_u32(QH);
    const uint32_t sQL = smem_u32(QL);
    const uint32_t sKH = smem_u32(KH);
    const uint32_t sKL = smem_u32(KL);
    const uint32_t sVH = smem_u32(VH);
    const uint32_t sVL = smem_u32(VL);

    /* ---- Q fragments into registers (held across kv loop) ---- */
    uint32_t qh[4][4], ql[4][4];
    {
        const uint32_t a0 =
            2u * ((uint32_t)((w * 16 + (lane & 15)) * ASTR) + ((lane >> 4) << 3));
#pragma unroll
        for (int ks = 0; ks < 4; ks++) {
            ldsm4(sQH + a0 + 2u * (ks * 16), qh[ks][0], qh[ks][1], qh[ks][2], qh[ks][3]);
            ldsm4(sQL + a0 + 2u * (ks * 16), ql[ks][0], ql[ks][1], ql[ks][2], ql[ks][3]);
        }
    }

    const uint32_t bpat = 2u * ((uint32_t)(((lane & 7) | ((lane & 16) >> 1)) * ASTR)
                                + (lane & 8));

    float o[8][4];
#pragma unroll
    for (int i = 0; i < 8; i++)
#pragma unroll
        for (int c = 0; c < 4; c++) o[i][c] = 0.f;
    float mrow0 = -INFINITY, mrow1 = -INFINITY;
    float lrow0 = 0.f, lrow1 = 0.f;

    const int qglo   = qt * 128 + w * 16;     /* warp's first q row */
    const int ntiles = 2 * qt + 2;

    for (int jt = 0; jt < ntiles; jt++) {
        __syncthreads();
        /* ---- load K tile ---- */
#pragma unroll
        for (int it = 0; it < 4; it++) {
            int idx = tid + it * 256;
            int r   = idx >> 4;
            int c4  = (idx & 15) * 4;
            float4 v = *reinterpret_cast<const float4*>(
                Kb + (size_t)(jt * 64 + r) * DH_ + c4);
            uint32_t h0, l0, h1, l1;
            split2(v.x, v.y, h0, l0);
            split2(v.z, v.w, h1, l1);
            *reinterpret_cast<uint2*>(KH + r * ASTR + c4) = make_uint2(h0, h1);
            *reinterpret_cast<uint2*>(KL + r * ASTR + c4) = make_uint2(l0, l1);
        }
        /* ---- load V tile transposed ---- */
#pragma unroll
        for (int it = 0; it < 4; it++) {
            int idx = tid + it * 256;
            int j   = idx >> 4;
            int d4  = (idx & 15) * 4;
            float4 v = *reinterpret_cast<const float4*>(
                Vb + (size_t)(jt * 64 + j) * DH_ + d4);
            float vv[4] = {v.x, v.y, v.z, v.w};
#pragma unroll
            for (int e = 0; e < 4; e++) {
                __nv_bfloat16 hi = __float2bfloat16(vv[e]);
                __nv_bfloat16 lo = __float2bfloat16(vv[e] - __bfloat162float(hi));
                VH[(d4 + e) * ASTR + j] = hi;
                VL[(d4 + e) * ASTR + j] = lo;
            }
        }
        __syncthreads();

        if (jt * 64 > qglo + 15) continue;    /* warp fully above diagonal */

        /* ---- S = Q K^T ---- */
        float s[8][4];
#pragma unroll
        for (int i = 0; i < 8; i++)
#pragma unroll
            for (int c = 0; c < 4; c++) s[i][c] = 0.f;

#pragma unroll
        for (int ks = 0; ks < 4; ks++) {
#pragma unroll
            for (int np = 0; np < 4; np++) {
                const uint32_t boff = bpat + 2u * (np * 16 * ASTR + ks * 16);
                uint32_t bh4[4], bl4[4];
                ldsm4(sKH + boff, bh4[0], bh4[1], bh4[2], bh4[3]);
                ldsm4(sKL + boff, bl4[0], bl4[1], bl4[2], bl4[3]);
#pragma unroll
                for (int sub = 0; sub < 2; sub++) {
                    float* c = s[np * 2 + sub];
                    mma16816(c, qh[ks][0], qh[ks][1], qh[ks][2], qh[ks][3],
                             bh4[sub * 2], bh4[sub * 2 + 1]);
                    mma16816(c, qh[ks][0], qh[ks][1], qh[ks][2], qh[ks][3],
                             bl4[sub * 2], bl4[sub * 2 + 1]);
                    mma16816(c, ql[ks][0], ql[ks][1], ql[ks][2], ql[ks][3],
                             bh4[sub * 2], bh4[sub * 2 + 1]);
                }
            }
        }

        /* ---- causal mask (diagonal-overlap tiles only) ---- */
        const int r0 = qglo + (lane >> 2);
        const int r1 = r0 + 8;
        if (jt * 64 + 63 > qglo) {
            const int colb = jt * 64 + (lane & 3) * 2;
#pragma unroll
            for (int nt = 0; nt < 8; nt++) {
                int c0 = colb + nt * 8;
                if (c0 > r0)     s[nt][0] = -INFINITY;
                if (c0 + 1 > r0) s[nt][1] = -INFINITY;
                if (c0 > r1)     s[nt][2] = -INFINITY;
                if (c0 + 1 > r1) s[nt][3] = -INFINITY;
            }
        }

        /* ---- online softmax ---- */
        float mt0 = s[0][0], mt1 = s[0][2];
#pragma unroll
        for (int nt = 0; nt < 8; nt++) {
            mt0 = fmaxf(mt0, fmaxf(s[nt][0], s[nt][1]));
            mt1 = fmaxf(mt1, fmaxf(s[nt][2], s[nt][3]));
        }
        mt0 = fmaxf(mt0, __shfl_xor_sync(0xffffffffu, mt0, 1));
        mt0 = fmaxf(mt0, __shfl_xor_sync(0xffffffffu, mt0, 2));
        mt1 = fmaxf(mt1, __shfl_xor_sync(0xffffffffu, mt1, 1));
        mt1 = fmaxf(mt1, __shfl_xor_sync(0xffffffffu, mt1, 2));

        const float mn0 = fmaxf(mrow0, mt0);
        const float mn1 = fmaxf(mrow1, mt1);
        const float al0 = __expf(mrow0 - mn0);
        const float al1 = __expf(mrow1 - mn1);

        float ps0 = 0.f, ps1 = 0.f;
#pragma unroll
        for (int nt = 0; nt < 8; nt++) {
            s[nt][0] = __expf(s[nt][0] - mn0);
            s[nt][1] = __expf(s[nt][1] - mn0);
            s[nt][2] = __expf(s[nt][2] - mn1);
            s[nt][3] = __expf(s[nt][3] - mn1);
            ps0 += s[nt][0] + s[nt][1];
            ps1 += s[nt][2] + s[nt][3];
        }
        ps0 += __shfl_xor_sync(0xffffffffu, ps0, 1);
        ps0 += __shfl_xor_sync(0xffffffffu, ps0, 2);
        ps1 += __shfl_xor_sync(0xffffffffu, ps1, 1);
        ps1 += __shfl_xor_sync(0xffffffffu, ps1, 2);

        lrow0 = lrow0 * al0 + ps0;
        lrow1 = lrow1 * al1 + ps1;
#pragma unroll
        for (int nt = 0; nt < 8; nt++) {
            o[nt][0] *= al0; o[nt][1] *= al0;
            o[nt][2] *= al1; o[nt][3] *= al1;
        }
        mrow0 = mn0;
        mrow1 = mn1;

        /* ---- O += P V ---- */
#pragma unroll
        for (int ks = 0; ks < 4; ks++) {
            uint32_t ph[4], pl[4];
            split2(s[2 * ks][0],     s[2 * ks][1],     ph[0], pl[0]);
            split2(s[2 * ks][2],     s[2 * ks][3],     ph[1], pl[1]);
            split2(s[2 * ks + 1][0], s[2 * ks + 1][1], ph[2], pl[2]);
            split2(s[2 * ks + 1][2], s[2 * ks + 1][3], ph[3], pl[3]);
#pragma unroll
            for (int np = 0; np < 4; np++) {
                const uint32_t boff = bpat + 2u * (np * 16 * ASTR + ks * 16);
                uint32_t bh4[4], bl4[4];
                ldsm4(sVH + boff, bh4[0], bh4[1], bh4[2], bh4[3]);
                ldsm4(sVL + boff, bl4[0], bl4[1], bl4[2], bl4[3]);
#pragma unroll
                for (int sub = 0; sub < 2; sub++) {
                    float* c = o[np * 2 + sub];
                    mma16816(c, ph[0], ph[1], ph[2], ph[3],
                             bh4[sub * 2], bh4[sub * 2 + 1]);
                    mma16816(c, ph[0], ph[1], ph[2], ph[3],
                             bl4[sub * 2], bl4[sub * 2 + 1]);
                    mma16816(c, pl[0], pl[1], pl[2], pl[3],
                             bh4[sub * 2], bh4[sub * 2 + 1]);
                }
            }
        }
    }

    /* ---- epilogue: normalize, write to g_ao[b,n,h*64+d] ---- */
    const float i0 = 1.f / lrow0;
    const float i1 = 1.f / lrow1;
    const int r0 = qt * 128 + w * 16 + (lane >> 2);
    float* dst0 = g_ao + ((size_t)b * N_ + r0) * D_ + h * DH_ + (lane & 3) * 2;
    float* dst1 = dst0 + 8 * D_;
#pragma unroll
    for (int nt = 0; nt < 8; nt++) {
        *reinterpret_cast<float2*>(dst0 + nt * 8) =
            make_float2(o[nt][0] * i0, o[nt][1] * i0);
        *reinterpret_cast<float2*>(dst1 + nt * 8) =
            make_float2(o[nt][2] * i1, o[nt][3] * i1);
    }
}

/* ------------------------------------------------------------------ */
extern "C" void kernel_launch(void* const* d_in, const int* in_sizes, int n_in,
                              void* d_out, int out_size)
{
    const float* x    = (const float*)d_in[0];
    /* d_in[1] = mask (static causal structure, unused) */
    const float* Wqkv = (const float*)d_in[2];
    const float* Wout = (const float*)d_in[3];
    float* out = (float*)d_out;

    float* ao_ptr = nullptr;
    cudaGetSymbolAddress((void**)&ao_ptr, g_ao);

    /* 1. QKV projection (HMMA bf16-split), scatter into [B,H,N,DH] */
    gemm_hmma<0><<<dim3(3072 / 128, 4096 / 128), 256>>>(x, Wqkv, nullptr, D_, 3 * D_);

    /* 2. causal flash attention (HMMA bf16-split) */
    const int ATT_SMEM = ATT_SMEM_ELEMS * (int)sizeof(__nv_bfloat16);  /* 73728 B */
    cudaFuncSetAttribute(attn_mma,
                         cudaFuncAttributeMaxDynamicSharedMemorySize, ATT_SMEM);
    attn_mma<<<dim3((N_ / 128) * 32), 256, ATT_SMEM>>>();

    /* 3. output projection (HMMA bf16-split) -> d_out */
    gemm_hmma<1><<<dim3(1024 / 128, 4096 / 128), 256>>>(ao_ptr, Wout, out, D_, D_);
}